// round 1
// baseline (speedup 1.0000x reference)
#include <cuda_runtime.h>

#define BATCH 32
#define NIN   2312
#define NHID  512
#define NOUT  10
#define TT    350
#define TKLEN 100

#define THETA 10.0f
// d = exp(-TS/TAU_SR) = exp(-0.1)
#define D_SR  0.90483741803595952f
// C_SR = e*TS/TAU_SR = e/10 (so eps[m] = C_SR * m * d^m)
#define C_SR  0.27182818284590452f
// d^100 = exp(-10)
#define E10   4.5399929762484854e-05f
// refractory: D_REF = exp(-TS/TAU_REF) = exp(-1)
#define D_REF 0.36787944117144233f
// C_REF = -scaleRef*theta*e*TS/tauRef = -20e
#define C_REF -54.365636569180902f

// scratch (allocation-free: device globals)
__device__ float g_G1[(size_t)BATCH * TT * NHID];   // [b][t][h]
__device__ float g_S1[(size_t)BATCH * TT * NHID];   // [b][t][h]
__device__ float g_G2[(size_t)BATCH * TT * NOUT];   // [b][t][o]

// ---------------------------------------------------------------------------
// GEMM1: G1[b][t][h] = sum_i W1[h][i] * X[b][i][t]
// X: [BATCH][NIN][TT], W1: [NHID][NIN]
// ---------------------------------------------------------------------------
#define BM 64
#define BN 64
#define BK 32

__global__ void __launch_bounds__(256) gemm1_kernel(const float* __restrict__ X,
                                                    const float* __restrict__ W1) {
    __shared__ float As[BK][BM];   // [k][h]
    __shared__ float Bs[BK][BN];   // [k][t]

    const int b  = blockIdx.z;
    const int h0 = blockIdx.y * BM;
    const int t0 = blockIdx.x * BN;
    const int tid = threadIdx.x;
    const int tx = tid & 15;   // h quad index (0..15)
    const int ty = tid >> 4;   // t quad index (0..15)

    float acc[4][4];           // acc[j(t)][i(h)]
    #pragma unroll
    for (int j = 0; j < 4; j++)
        #pragma unroll
        for (int i = 0; i < 4; i++) acc[j][i] = 0.f;

    for (int k0 = 0; k0 < NIN; k0 += BK) {
        // Load A tile: W1[h0+r][k0+c] -> As[c][r]
        #pragma unroll
        for (int j = 0; j < 2; j++) {
            int fid = tid * 2 + j;          // 0..511 (64 rows x 8 float4-cols)
            int r   = fid >> 3;
            int c4  = (fid & 7) * 4;
            #pragma unroll
            for (int cc = 0; cc < 4; cc++) {
                int c  = c4 + cc;
                int gk = k0 + c;
                As[c][r] = (gk < NIN) ? W1[(size_t)(h0 + r) * NIN + gk] : 0.f;
            }
        }
        // Load B tile: X[b][k0+kk][t0+c] -> Bs[kk][c]
        #pragma unroll
        for (int j = 0; j < 2; j++) {
            int fid = tid * 2 + j;          // 0..511 (32 rows x 16 float4-cols)
            int kk  = fid >> 4;
            int c4  = (fid & 15) * 4;
            const bool krow = (k0 + kk) < NIN;
            const float* xrow = X + ((size_t)b * NIN + (k0 + kk)) * TT;
            #pragma unroll
            for (int cc = 0; cc < 4; cc++) {
                int t = t0 + c4 + cc;
                Bs[kk][c4 + cc] = (krow && t < TT) ? xrow[t] : 0.f;
            }
        }
        __syncthreads();

        #pragma unroll
        for (int kk = 0; kk < BK; kk++) {
            float4 a  = *(const float4*)&As[kk][tx * 4];
            float4 bb = *(const float4*)&Bs[kk][ty * 4];
            float av[4] = {a.x, a.y, a.z, a.w};
            float bv[4] = {bb.x, bb.y, bb.z, bb.w};
            #pragma unroll
            for (int j = 0; j < 4; j++)
                #pragma unroll
                for (int i = 0; i < 4; i++)
                    acc[j][i] = fmaf(av[i], bv[j], acc[j][i]);
        }
        __syncthreads();
    }

    // Store: G1[b][t][h0+tx*4 .. +3], h-contiguous float4
    #pragma unroll
    for (int j = 0; j < 4; j++) {
        int t = t0 + ty * 4 + j;
        if (t < TT) {
            float4 v = make_float4(acc[j][0], acc[j][1], acc[j][2], acc[j][3]);
            *(float4*)&g_G1[((size_t)b * TT + t) * NHID + h0 + tx * 4] = v;
        }
    }
}

// ---------------------------------------------------------------------------
// scan1: per (b,h) channel — truncated-alpha psp via 4-state IIR fused with
// the threshold/refractory spike scan. Writes s1 in {0,1}.
// ---------------------------------------------------------------------------
__global__ void __launch_bounds__(256) scan1_kernel() {
    int idx = blockIdx.x * blockDim.x + threadIdx.x;
    if (idx >= BATCH * NHID) return;
    int b = idx / NHID;
    int h = idx - b * NHID;

    const float* g = g_G1 + (size_t)b * TT * NHID + h;  // stride NHID over t
    float*       s = g_S1 + (size_t)b * TT * NHID + h;

    float pa = 0.f, pb = 0.f;   // full alpha IIR
    float qa = 0.f, qb = 0.f;   // delayed (tail-correction) alpha IIR
    float ra = 0.f, rb = 0.f;   // refractory alpha IIR

    for (int t = 0; t < TT; t++) {
        float gv = g[(size_t)t * NHID];
        float gd = (t >= TKLEN) ? g[(size_t)(t - TKLEN) * NHID] : 0.f;

        float pa_o = pa, qa_o = qa, ra_o = ra;
        pa = fmaf(D_SR, pa_o, gv);
        pb = fmaf(D_SR, pb, D_SR * pa_o);
        qa = fmaf(D_SR, qa_o, gd);
        qb = fmaf(D_SR, qb, D_SR * qa_o);

        // truncated psp: y = C_SR * (pb - d^100*(100*qa + qb))
        float y = C_SR * (pb - E10 * fmaf(100.f, qa, qb));
        float u = fmaf(C_REF, rb, y);
        float sp = (u >= THETA) ? 1.f : 0.f;

        ra = fmaf(D_REF, ra_o, sp);
        rb = fmaf(D_REF, rb, D_REF * ra_o);

        s[(size_t)t * NHID] = sp;
    }
}

// ---------------------------------------------------------------------------
// GEMM2: G2[b][t][o] = sum_h W2[o][h] * S1[b][t][h]. One warp per (b,t).
// ---------------------------------------------------------------------------
__global__ void __launch_bounds__(256) gemm2_kernel(const float* __restrict__ W2) {
    __shared__ float w2s[NOUT * NHID];  // 20 KB
    for (int i = threadIdx.x; i < NOUT * NHID; i += 256) w2s[i] = W2[i];
    __syncthreads();

    int gw   = (blockIdx.x * 256 + threadIdx.x) >> 5;
    int lane = threadIdx.x & 31;
    if (gw >= BATCH * TT) return;
    int b = gw / TT;
    int t = gw - b * TT;

    const float* srow = g_S1 + ((size_t)b * TT + t) * NHID;

    float acc[NOUT];
    #pragma unroll
    for (int o = 0; o < NOUT; o++) acc[o] = 0.f;

    for (int h = lane; h < NHID; h += 32) {
        float sv = srow[h];
        #pragma unroll
        for (int o = 0; o < NOUT; o++)
            acc[o] = fmaf(w2s[o * NHID + h], sv, acc[o]);
    }
    #pragma unroll
    for (int off = 16; off > 0; off >>= 1)
        #pragma unroll
        for (int o = 0; o < NOUT; o++)
            acc[o] += __shfl_xor_sync(0xffffffffu, acc[o], off);

    if (lane == 0) {
        #pragma unroll
        for (int o = 0; o < NOUT; o++)
            g_G2[((size_t)b * TT + t) * NOUT + o] = acc[o];
    }
}

// ---------------------------------------------------------------------------
// scan2: per (b,o) channel — same fused psp-IIR + spike scan; writes final
// output in [b][o][t] layout.
// ---------------------------------------------------------------------------
__global__ void __launch_bounds__(128) scan2_kernel(float* __restrict__ out) {
    int idx = blockIdx.x * blockDim.x + threadIdx.x;
    if (idx >= BATCH * NOUT) return;
    int b = idx / NOUT;
    int o = idx - b * NOUT;

    const float* g = g_G2 + (size_t)b * TT * NOUT + o;     // stride NOUT over t
    float*       y_out = out + ((size_t)b * NOUT + o) * TT; // contiguous t

    float pa = 0.f, pb = 0.f, qa = 0.f, qb = 0.f, ra = 0.f, rb = 0.f;

    for (int t = 0; t < TT; t++) {
        float gv = g[(size_t)t * NOUT];
        float gd = (t >= TKLEN) ? g[(size_t)(t - TKLEN) * NOUT] : 0.f;

        float pa_o = pa, qa_o = qa, ra_o = ra;
        pa = fmaf(D_SR, pa_o, gv);
        pb = fmaf(D_SR, pb, D_SR * pa_o);
        qa = fmaf(D_SR, qa_o, gd);
        qb = fmaf(D_SR, qb, D_SR * qa_o);

        float y = C_SR * (pb - E10 * fmaf(100.f, qa, qb));
        float u = fmaf(C_REF, rb, y);
        float sp = (u >= THETA) ? 1.f : 0.f;

        ra = fmaf(D_REF, ra_o, sp);
        rb = fmaf(D_REF, rb, D_REF * ra_o);

        y_out[t] = sp;
    }
}

// ---------------------------------------------------------------------------
extern "C" void kernel_launch(void* const* d_in, const int* in_sizes, int n_in,
                              void* d_out, int out_size) {
    const float* X  = (const float*)d_in[0];   // [32][2312][350]
    const float* W1 = (const float*)d_in[1];   // [512][2312]
    const float* W2 = (const float*)d_in[2];   // [10][512]
    float* out = (float*)d_out;                // [32][10][350]

    dim3 grid1((TT + BN - 1) / BN, NHID / BM, BATCH);
    gemm1_kernel<<<grid1, 256>>>(X, W1);

    scan1_kernel<<<(BATCH * NHID + 255) / 256, 256>>>();

    int warps = BATCH * TT;                     // one warp per (b,t)
    gemm2_kernel<<<(warps * 32 + 255) / 256, 256>>>(W2);

    scan2_kernel<<<(BATCH * NOUT + 127) / 128, 128>>>(out);
}

// round 2
// speedup vs baseline: 5.4599x; 5.4599x over previous
#include <cuda_runtime.h>

#define BATCH 32
#define NIN   2312
#define NHID  512
#define NOUT  10
#define TT    350
#define TKLEN 100

#define THETA 10.0f
#define D_SR  0.90483741803595952f     // exp(-0.1)
#define C_SR  0.27182818284590452f     // e/10
#define E10   4.5399929762484854e-05f  // exp(-10)
#define D_REF 0.36787944117144233f     // exp(-1)
#define C_REF -54.365636569180902f     // -20e

// scratch (allocation-free: device globals)
__device__ float g_W1T[(size_t)NIN * NHID];         // [i][h]
__device__ float g_G1[(size_t)BATCH * TT * NHID];   // [b][t][h]
__device__ float g_S1[(size_t)BATCH * TT * NHID];   // [b][t][h]

// ---------------------------------------------------------------------------
// Transpose W1 [NHID][NIN] -> W1T [NIN][NHID]
// ---------------------------------------------------------------------------
__global__ void __launch_bounds__(256) w1t_kernel(const float* __restrict__ W1) {
    __shared__ float tile[32][33];
    int i0 = blockIdx.x * 32;   // NIN dim
    int h0 = blockIdx.y * 32;   // NHID dim
    int lx = threadIdx.x & 31;
    int ly = threadIdx.x >> 5;  // 0..7

    #pragma unroll
    for (int r = 0; r < 4; r++) {
        int h = h0 + ly + r * 8;
        int i = i0 + lx;
        tile[ly + r * 8][lx] = (i < NIN) ? W1[(size_t)h * NIN + i] : 0.f;
    }
    __syncthreads();
    #pragma unroll
    for (int r = 0; r < 4; r++) {
        int i = i0 + ly + r * 8;
        int h = h0 + lx;
        if (i < NIN) g_W1T[(size_t)i * NHID + h] = tile[lx][ly + r * 8];
    }
}

// ---------------------------------------------------------------------------
// Sparse GEMM1: warp per (b,t). X binary -> G1[b][t][:] = sum of active W1T rows.
// Deterministic ascending-i accumulation order via ballot + ffs.
// Blocks: 8 warps = 8 consecutive t for one b (X sector reuse in L1).
// ---------------------------------------------------------------------------
__global__ void __launch_bounds__(256) spgemm1_kernel(const float* __restrict__ X) {
    const int warp = threadIdx.x >> 5;
    const int lane = threadIdx.x & 31;
    const int b  = blockIdx.y;
    const int t  = blockIdx.x * 8 + warp;
    if (t >= TT) return;

    const float* xcol = X + (size_t)b * NIN * TT + t;   // stride TT over i

    float4 acc0 = make_float4(0.f, 0.f, 0.f, 0.f);
    float4 acc1 = acc0, acc2 = acc0, acc3 = acc0;

    for (int c = 0; c < NIN; c += 32) {
        int i = c + lane;
        float xv = (i < NIN) ? __ldg(&xcol[(size_t)i * TT]) : 0.f;
        unsigned m = __ballot_sync(0xffffffffu, xv != 0.f);
        while (m) {
            int j = __ffs(m) - 1;
            m &= m - 1;
            const float4* row = (const float4*)(g_W1T + (size_t)(c + j) * NHID);
            float4 r0 = row[lane];
            float4 r1 = row[lane + 32];
            float4 r2 = row[lane + 64];
            float4 r3 = row[lane + 96];
            acc0.x += r0.x; acc0.y += r0.y; acc0.z += r0.z; acc0.w += r0.w;
            acc1.x += r1.x; acc1.y += r1.y; acc1.z += r1.z; acc1.w += r1.w;
            acc2.x += r2.x; acc2.y += r2.y; acc2.z += r2.z; acc2.w += r2.w;
            acc3.x += r3.x; acc3.y += r3.y; acc3.z += r3.z; acc3.w += r3.w;
        }
    }

    float4* out = (float4*)(g_G1 + ((size_t)b * TT + t) * NHID);
    out[lane]      = acc0;
    out[lane + 32] = acc1;
    out[lane + 64] = acc2;
    out[lane + 96] = acc3;
}

// ---------------------------------------------------------------------------
// scan1: per (b,h) channel — truncated-alpha psp (4-state IIR) fused with
// threshold/refractory spike scan. Writes s1 in {0,1}.
// ---------------------------------------------------------------------------
__global__ void __launch_bounds__(256) scan1_kernel() {
    int idx = blockIdx.x * blockDim.x + threadIdx.x;
    if (idx >= BATCH * NHID) return;
    int b = idx / NHID;
    int h = idx - b * NHID;

    const float* __restrict__ g = g_G1 + (size_t)b * TT * NHID + h;
    float*       __restrict__ s = g_S1 + (size_t)b * TT * NHID + h;

    float pa = 0.f, pb = 0.f;
    float qa = 0.f, qb = 0.f;
    float ra = 0.f, rb = 0.f;

    #pragma unroll 5
    for (int t = 0; t < TT; t++) {
        float gv = __ldg(&g[(size_t)t * NHID]);
        float gd = (t >= TKLEN) ? __ldg(&g[(size_t)(t - TKLEN) * NHID]) : 0.f;

        float pa_o = pa, qa_o = qa, ra_o = ra;
        pa = fmaf(D_SR, pa_o, gv);
        pb = fmaf(D_SR, pb, D_SR * pa_o);
        qa = fmaf(D_SR, qa_o, gd);
        qb = fmaf(D_SR, qb, D_SR * qa_o);

        float y = C_SR * (pb - E10 * fmaf(100.f, qa, qb));
        float u = fmaf(C_REF, rb, y);
        float sp = (u >= THETA) ? 1.f : 0.f;

        ra = fmaf(D_REF, ra_o, sp);
        rb = fmaf(D_REF, rb, D_REF * ra_o);

        s[(size_t)t * NHID] = sp;
    }
}

// ---------------------------------------------------------------------------
// Fused GEMM2 + scan2: one block per batch b.
//   Phase 1: warps compute G2[t][o] = sum_h W2[o][h]*S1[b][t][h] into smem.
//   Phase 2: threads 0..9 run the spike scan over t from smem; write output.
// ---------------------------------------------------------------------------
__global__ void __launch_bounds__(256) tail_kernel(const float* __restrict__ W2,
                                                   float* __restrict__ out) {
    __shared__ float w2s[NOUT * NHID];   // 20 KB
    __shared__ float g2s[TT * NOUT];     // 14 KB

    const int b = blockIdx.x;
    const int warp = threadIdx.x >> 5;
    const int lane = threadIdx.x & 31;

    for (int i = threadIdx.x; i < NOUT * NHID; i += 256) w2s[i] = W2[i];
    __syncthreads();

    for (int t = warp; t < TT; t += 8) {
        const float* srow = g_S1 + ((size_t)b * TT + t) * NHID;
        float acc[NOUT];
        #pragma unroll
        for (int o = 0; o < NOUT; o++) acc[o] = 0.f;

        for (int h = lane; h < NHID; h += 32) {
            float sv = srow[h];
            #pragma unroll
            for (int o = 0; o < NOUT; o++)
                acc[o] = fmaf(w2s[o * NHID + h], sv, acc[o]);
        }
        #pragma unroll
        for (int off = 16; off > 0; off >>= 1)
            #pragma unroll
            for (int o = 0; o < NOUT; o++)
                acc[o] += __shfl_xor_sync(0xffffffffu, acc[o], off);

        if (lane == 0) {
            #pragma unroll
            for (int o = 0; o < NOUT; o++)
                g2s[t * NOUT + o] = acc[o];
        }
    }
    __syncthreads();

    if (threadIdx.x < NOUT) {
        const int o = threadIdx.x;
        float* y_out = out + ((size_t)b * NOUT + o) * TT;

        float pa = 0.f, pb = 0.f, qa = 0.f, qb = 0.f, ra = 0.f, rb = 0.f;
        for (int t = 0; t < TT; t++) {
            float gv = g2s[t * NOUT + o];
            float gd = (t >= TKLEN) ? g2s[(t - TKLEN) * NOUT + o] : 0.f;

            float pa_o = pa, qa_o = qa, ra_o = ra;
            pa = fmaf(D_SR, pa_o, gv);
            pb = fmaf(D_SR, pb, D_SR * pa_o);
            qa = fmaf(D_SR, qa_o, gd);
            qb = fmaf(D_SR, qb, D_SR * qa_o);

            float y = C_SR * (pb - E10 * fmaf(100.f, qa, qb));
            float u = fmaf(C_REF, rb, y);
            float sp = (u >= THETA) ? 1.f : 0.f;

            ra = fmaf(D_REF, ra_o, sp);
            rb = fmaf(D_REF, rb, D_REF * ra_o);

            y_out[t] = sp;
        }
    }
}

// ---------------------------------------------------------------------------
extern "C" void kernel_launch(void* const* d_in, const int* in_sizes, int n_in,
                              void* d_out, int out_size) {
    const float* X  = (const float*)d_in[0];   // [32][2312][350]
    const float* W1 = (const float*)d_in[1];   // [512][2312]
    const float* W2 = (const float*)d_in[2];   // [10][512]
    float* out = (float*)d_out;                // [32][10][350]

    dim3 gT((NIN + 31) / 32, NHID / 32);
    w1t_kernel<<<gT, 256>>>(W1);

    dim3 gS((TT + 7) / 8, BATCH);
    spgemm1_kernel<<<gS, 256>>>(X);

    scan1_kernel<<<(BATCH * NHID + 255) / 256, 256>>>();

    tail_kernel<<<BATCH, 256>>>(W2, out);
}